// round 5
// baseline (speedup 1.0000x reference)
#include <cuda_runtime.h>
#include <cuda_bf16.h>
#include <math.h>

// Problem constants
#define DIMP  1024           // patch_dim
#define NK    1024           // num_atoms
#define NB    8192           // batch
#define SPAR  8              // sparsity
#define DIAG_EPS_F 1e-4f
#define CHOL_EPS_F 1e-6f

// Scratch (device globals; no cudaMalloc allowed)
__device__ float g_G[(size_t)NK * NK];        // Gram matrix, 4 MB
__device__ float g_hbar[(size_t)NB * NK];     // correlations, 32 MB

// ---------------------------------------------------------------------------
// TN GEMM: C[m,n] = sum_d A[d,m] * B[d,n]  (+ diagEps on diagonal if != 0)
// A: [Dd, M] row-major (lda = M), B: [Dd, N] row-major (ldb = N), C: [M, N]
// 128x128 tile, 256 threads, k-chunk 8, fp32 FFMA.
// Double-buffered SMEM: one __syncthreads per k-chunk, global loads for
// chunk k+1 overlap the 512 FFMAs of chunk k.
// ---------------------------------------------------------------------------
__global__ __launch_bounds__(256, 2)
void gemm_tn(const float* __restrict__ A, const float* __restrict__ Bm,
             float* __restrict__ C, int M, int N, int Dd, float diagEps)
{
    __shared__ float As[2][8][128];
    __shared__ float Bs[2][8][128];

    const int tid = threadIdx.x;
    const int mBase = blockIdx.y * 128;
    const int nBase = blockIdx.x * 128;

    // loader mapping: 8 rows x 32 float4 columns
    const int lrow = tid >> 5;         // 0..7
    const int lc4  = (tid & 31) * 4;   // 0,4,...,124

    // compute mapping: 16x16 threads, each 8x8 outputs
    const int tx = tid & 15;           // col group
    const int ty = tid >> 4;           // row group

    const float* aPtr = A + (size_t)lrow * M + mBase + lc4;
    const float* bPtr = Bm + (size_t)lrow * N + nBase + lc4;

    float acc[8][8];
#pragma unroll
    for (int i = 0; i < 8; i++)
#pragma unroll
        for (int j = 0; j < 8; j++) acc[i][j] = 0.f;

    // prologue: chunk 0 -> buffer 0
    {
        const float4 av = *reinterpret_cast<const float4*>(aPtr);
        const float4 bv = *reinterpret_cast<const float4*>(bPtr);
        *reinterpret_cast<float4*>(&As[0][lrow][lc4]) = av;
        *reinterpret_cast<float4*>(&Bs[0][lrow][lc4]) = bv;
    }
    __syncthreads();

    for (int d0 = 0; d0 < Dd; d0 += 8) {
        const int cur = (d0 >> 3) & 1;
        const bool hasNext = (d0 + 8) < Dd;

        // prefetch next chunk into registers (overlaps with compute below)
        float4 avn, bvn;
        if (hasNext) {
            avn = *reinterpret_cast<const float4*>(aPtr + (size_t)(d0 + 8) * M);
            bvn = *reinterpret_cast<const float4*>(bPtr + (size_t)(d0 + 8) * N);
        }

        // compute current chunk
#pragma unroll
        for (int dk = 0; dk < 8; dk++) {
            float a[8], b[8];
#pragma unroll
            for (int i = 0; i < 4; i++) {
                a[i]     = As[cur][dk][ty * 8 + i];
                a[i + 4] = As[cur][dk][ty * 8 + 4 + i];
                b[i]     = Bs[cur][dk][tx * 8 + i];
                b[i + 4] = Bs[cur][dk][tx * 8 + 4 + i];
            }
#pragma unroll
            for (int i = 0; i < 8; i++)
#pragma unroll
                for (int j = 0; j < 8; j++)
                    acc[i][j] = fmaf(a[i], b[j], acc[i][j]);
        }

        // stage next chunk into the other buffer
        if (hasNext) {
            const int nxt = 1 - cur;
            *reinterpret_cast<float4*>(&As[nxt][lrow][lc4]) = avn;
            *reinterpret_cast<float4*>(&Bs[nxt][lrow][lc4]) = bvn;
            __syncthreads();
        }
    }

    // epilogue
#pragma unroll
    for (int i = 0; i < 8; i++) {
        const int r = mBase + ty * 8 + i;
        float* crow = C + (size_t)r * N + nBase + tx * 8;
#pragma unroll
        for (int j = 0; j < 8; j++) {
            float v = acc[i][j];
            if (diagEps != 0.f && r == (nBase + tx * 8 + j)) v += diagEps;
            crow[j] = v;
        }
    }
}

// ---------------------------------------------------------------------------
// Per-batch OMP: one CTA per batch element. 256 threads.
// h/h_bar rows live in SMEM; tiny Cholesky + solves on thread 0;
// beta update reads <=8 rows of G (L2-resident) per step.
// ---------------------------------------------------------------------------
__device__ __forceinline__ float n2n(float v) {
    return isfinite(v) ? v : 0.f;
}

__global__ __launch_bounds__(256)
void omp_kernel(const float* __restrict__ G, const float* __restrict__ hbar,
                float* __restrict__ out, int out_size)
{
    const int b = blockIdx.x;
    const int tid = threadIdx.x;

    __shared__ float hb[NK];
    __shared__ float h[NK];
    __shared__ int   sI[SPAR];
    __shared__ float sL[SPAR][SPAR];
    __shared__ float sC[SPAR];
    __shared__ float g_new[SPAR];
    __shared__ float hst[SPAR];
    __shared__ float rv[8];
    __shared__ int   ri[8];
    __shared__ int   sSel;

    // load h_bar row (each thread owns one float4: columns [4*tid, 4*tid+4))
    {
        const float4 v = reinterpret_cast<const float4*>(hbar + (size_t)b * NK)[tid];
        float4 vn; vn.x = n2n(v.x); vn.y = n2n(v.y); vn.z = n2n(v.z); vn.w = n2n(v.w);
        reinterpret_cast<float4*>(h)[tid] = vn;
        reinterpret_cast<float4*>(hb)[tid] = vn;
    }
    __syncthreads();

    for (int step = 0; step < SPAR; step++) {
        // ---- argmax of scores = masked ? -1 : |h|, first-index tiebreak ----
        float best = -1e30f; int bi = 0;
#pragma unroll
        for (int u = 0; u < 4; u++) {
            const int c = tid * 4 + u;
            float v = fabsf(h[c]);
            bool masked = false;
#pragma unroll
            for (int j = 0; j < SPAR; j++)
                if (j < step && sI[j] == c) masked = true;
            if (masked) v = -1.0f;
            if (v > best || (v == best && c < bi)) { best = v; bi = c; }
        }
#pragma unroll
        for (int off = 16; off; off >>= 1) {
            const float ov = __shfl_down_sync(0xffffffffu, best, off);
            const int   oi = __shfl_down_sync(0xffffffffu, bi, off);
            if (ov > best || (ov == best && oi < bi)) { best = ov; bi = oi; }
        }
        if ((tid & 31) == 0) { rv[tid >> 5] = best; ri[tid >> 5] = bi; }
        __syncthreads();
        if (tid == 0) {
            float bb = rv[0]; int ii = ri[0];
#pragma unroll
            for (int w = 1; w < 8; w++)
                if (rv[w] > bb || (rv[w] == bb && ri[w] < ii)) { bb = rv[w]; ii = ri[w]; }
            sSel = ii;
            sI[step] = ii;
        }
        __syncthreads();
        const int idx = sSel;

        // ---- gather G[I_j, idx] and h_bar[I_j] in parallel lanes ----
        if (tid < step)  g_new[tid] = G[(size_t)sI[tid] * NK + idx];
        if (tid <= step) hst[tid]   = hb[sI[tid]];
        __syncthreads();

        // ---- Cholesky update + cho_solve (serial, tiny) ----
        if (tid == 0) {
            const float dg = G[(size_t)idx * NK + idx];
            if (step == 0) {
                sL[0][0] = sqrtf(fmaxf(dg, CHOL_EPS_F));
            } else {
                float w[SPAR];
                float ss = 0.f;
                for (int j = 0; j < step; j++) {
                    float a = g_new[j];
                    for (int m = 0; m < j; m++) a -= sL[j][m] * w[m];
                    w[j] = a / sL[j][j];
                    sL[step][j] = w[j];
                    ss += w[j] * w[j];
                }
                sL[step][step] = sqrtf(fmaxf(dg - ss, CHOL_EPS_F));
            }
            const int n = step + 1;
            float y[SPAR], x[SPAR];
            for (int j = 0; j < n; j++) {
                float a = hst[j];
                for (int m = 0; m < j; m++) a -= sL[j][m] * y[m];
                y[j] = a / sL[j][j];
            }
            for (int j = n - 1; j >= 0; j--) {
                float a = y[j];
                for (int m = j + 1; m < n; m++) a -= sL[m][j] * x[m];
                x[j] = a / sL[j][j];
            }
            for (int j = 0; j < n; j++) sC[j] = n2n(x[j]);
        }
        __syncthreads();

        // ---- h = n2n(h_bar - coeffs · G[I]) (skip after final step) ----
        if (step < SPAR - 1) {
            float4 a = make_float4(0.f, 0.f, 0.f, 0.f);
#pragma unroll
            for (int j = 0; j < SPAR; j++) {
                if (j > step) break;
                const float c = sC[j];
                const float4 g = reinterpret_cast<const float4*>(
                    G + (size_t)sI[j] * NK)[tid];
                a.x = fmaf(c, g.x, a.x);
                a.y = fmaf(c, g.y, a.y);
                a.z = fmaf(c, g.z, a.z);
                a.w = fmaf(c, g.w, a.w);
            }
            const float4 hbv = reinterpret_cast<const float4*>(hb)[tid];
            float4 hv;
            hv.x = n2n(hbv.x - a.x);
            hv.y = n2n(hbv.y - a.y);
            hv.z = n2n(hbv.z - a.z);
            hv.w = n2n(hbv.w - a.w);
            reinterpret_cast<float4*>(h)[tid] = hv;
            __syncthreads();
        }
    }

    // ---- output: indices (as float) then coefficients ----
    if (tid < SPAR) {
        const size_t iOff = (size_t)b * SPAR + tid;
        const size_t cOff = (size_t)NB * SPAR + (size_t)b * SPAR + tid;
        if (iOff < (size_t)out_size) out[iOff] = (float)sI[tid];
        if (cOff < (size_t)out_size) out[cOff] = sC[tid];
    }
}

// ---------------------------------------------------------------------------
extern "C" void kernel_launch(void* const* d_in, const int* in_sizes, int n_in,
                              void* d_out, int out_size)
{
    const float* X = (const float*)d_in[0];   // [1024, 8192]
    const float* D = (const float*)d_in[1];   // [1024, 1024]
    float* out = (float*)d_out;

    float* Gp;  cudaGetSymbolAddress((void**)&Gp, g_G);
    float* Hp;  cudaGetSymbolAddress((void**)&Hp, g_hbar);

    // G = D^T D + eps I   (M=N=1024)
    {
        dim3 grid(NK / 128, NK / 128);
        gemm_tn<<<grid, 256>>>(D, D, Gp, NK, NK, DIMP, DIAG_EPS_F);
    }
    // h_bar = X^T D       (M=8192, N=1024)
    {
        dim3 grid(NK / 128, NB / 128);
        gemm_tn<<<grid, 256>>>(X, D, Hp, NB, NK, DIMP, 0.f);
    }
    // per-batch OMP
    omp_kernel<<<NB, 256>>>(Gp, Hp, out, out_size);
}

// round 16
// speedup vs baseline: 1.2234x; 1.2234x over previous
#include <cuda_runtime.h>
#include <cuda_bf16.h>
#include <math.h>

// Problem constants
#define DIMP  1024           // patch_dim
#define NK    1024           // num_atoms
#define NB    8192           // batch
#define SPAR  8              // sparsity
#define DIAG_EPS_F 1e-4f
#define CHOL_EPS_F 1e-6f

// Scratch (device globals; no cudaMalloc allowed)
__device__ float g_G[(size_t)NK * NK];        // Gram matrix, 4 MB
__device__ float g_hbar[(size_t)NB * NK];     // correlations, 32 MB

// ---------------------------------------------------------------------------
// Fused TN GEMM: one launch computes both
//   h_bar = X^T D   (blocks [0, 512))   M=8192
//   G = D^T D + eps (blocks [512, 576)) M=1024
// C[m,n] = sum_d A[d,m] * B[d,n]; A:[Dd,M] (lda=M), B:[Dd,N] (ldb=N).
// 128x128 tile, 256 threads, k-chunk 8, double-buffered SMEM.
// Inner product uses packed fma.rn.f32x2 (FFMA2): 2 IEEE fp32 FMAs per
// instruction -> 2x the fp32 FMA-pipe throughput, bitwise fp32 semantics.
// ---------------------------------------------------------------------------
__device__ __forceinline__ void gemm_tile(
    const float* __restrict__ A, const float* __restrict__ Bm,
    float* __restrict__ C, int M, int N, int Dd, float diagEps,
    int bx, int by,
    float (*As)[8][128], float (*Bs)[8][128])
{
    const int tid = threadIdx.x;
    const int mBase = by * 128;
    const int nBase = bx * 128;

    // loader mapping: 8 rows x 32 float4 columns
    const int lrow = tid >> 5;         // 0..7
    const int lc4  = (tid & 31) * 4;   // 0,4,...,124

    // compute mapping: 16x16 threads, each 8x8 outputs (as 8x4 f32x2 pairs)
    const int tx = tid & 15;           // col group
    const int ty = tid >> 4;           // row group

    const float* aPtr = A + (size_t)lrow * M + mBase + lc4;
    const float* bPtr = Bm + (size_t)lrow * N + nBase + lc4;

    unsigned long long acc2[8][4];
#pragma unroll
    for (int i = 0; i < 8; i++)
#pragma unroll
        for (int j = 0; j < 4; j++) acc2[i][j] = 0ULL;

    // prologue: chunk 0 -> buffer 0
    {
        const float4 av = *reinterpret_cast<const float4*>(aPtr);
        const float4 bv = *reinterpret_cast<const float4*>(bPtr);
        *reinterpret_cast<float4*>(&As[0][lrow][lc4]) = av;
        *reinterpret_cast<float4*>(&Bs[0][lrow][lc4]) = bv;
    }
    __syncthreads();

    for (int d0 = 0; d0 < Dd; d0 += 8) {
        const int cur = (d0 >> 3) & 1;
        const bool hasNext = (d0 + 8) < Dd;

        // prefetch next chunk into registers (overlaps with compute below)
        float4 avn, bvn;
        if (hasNext) {
            avn = *reinterpret_cast<const float4*>(aPtr + (size_t)(d0 + 8) * M);
            bvn = *reinterpret_cast<const float4*>(bPtr + (size_t)(d0 + 8) * N);
        }

        // compute current chunk with packed f32x2 FMAs
#pragma unroll
        for (int dk = 0; dk < 8; dk++) {
            // a fragment: 8 scalars (two LDS.128)
            float a[8];
#pragma unroll
            for (int i = 0; i < 4; i++) {
                a[i]     = As[cur][dk][ty * 8 + i];
                a[i + 4] = As[cur][dk][ty * 8 + 4 + i];
            }
            // b fragment: 4 packed f32x2 pairs (two LDS.128)
            const ulonglong2 blo = *reinterpret_cast<const ulonglong2*>(&Bs[cur][dk][tx * 8]);
            const ulonglong2 bhi = *reinterpret_cast<const ulonglong2*>(&Bs[cur][dk][tx * 8 + 4]);
            unsigned long long b2[4];
            b2[0] = blo.x; b2[1] = blo.y; b2[2] = bhi.x; b2[3] = bhi.y;

#pragma unroll
            for (int i = 0; i < 8; i++) {
                unsigned long long ad;
                asm("mov.b64 %0, {%1, %1};" : "=l"(ad) : "f"(a[i]));
#pragma unroll
                for (int j = 0; j < 4; j++)
                    asm("fma.rn.f32x2 %0, %1, %2, %0;"
                        : "+l"(acc2[i][j]) : "l"(ad), "l"(b2[j]));
            }
        }

        // stage next chunk into the other buffer
        if (hasNext) {
            const int nxt = 1 - cur;
            *reinterpret_cast<float4*>(&As[nxt][lrow][lc4]) = avn;
            *reinterpret_cast<float4*>(&Bs[nxt][lrow][lc4]) = bvn;
            __syncthreads();
        }
    }

    // epilogue
#pragma unroll
    for (int i = 0; i < 8; i++) {
        const int r = mBase + ty * 8 + i;
        float* crow = C + (size_t)r * N + nBase + tx * 8;
#pragma unroll
        for (int j = 0; j < 4; j++) {
            float lo, hi;
            asm("mov.b64 {%0, %1}, %2;" : "=f"(lo), "=f"(hi) : "l"(acc2[i][j]));
            const int c0 = nBase + tx * 8 + 2 * j;
            if (diagEps != 0.f) {
                if (r == c0)     lo += diagEps;
                if (r == c0 + 1) hi += diagEps;
            }
            crow[2 * j]     = lo;
            crow[2 * j + 1] = hi;
        }
    }
}

__global__ __launch_bounds__(256, 2)
void gemm_fused(const float* __restrict__ X, const float* __restrict__ D,
                float* __restrict__ Hp, float* __restrict__ Gp)
{
    __shared__ float As[2][8][128];
    __shared__ float Bs[2][8][128];

    const int blk = blockIdx.x;
    if (blk < (NB / 128) * (NK / 128)) {
        // h_bar = X^T D : M=NB, N=NK
        const int bx = blk & 7;          // NK/128 = 8
        const int by = blk >> 3;
        gemm_tile(X, D, Hp, NB, NK, DIMP, 0.f, bx, by, As, Bs);
    } else {
        // G = D^T D + eps I : M=N=NK
        const int t = blk - (NB / 128) * (NK / 128);
        const int bx = t & 7;
        const int by = t >> 3;
        gemm_tile(D, D, Gp, NK, NK, DIMP, DIAG_EPS_F, bx, by, As, Bs);
    }
}

// ---------------------------------------------------------------------------
// Per-batch OMP: one CTA per batch element. 256 threads.
// ---------------------------------------------------------------------------
__device__ __forceinline__ float n2n(float v) {
    return isfinite(v) ? v : 0.f;
}

__global__ __launch_bounds__(256)
void omp_kernel(const float* __restrict__ G, const float* __restrict__ hbar,
                float* __restrict__ out, int out_size)
{
    const int b = blockIdx.x;
    const int tid = threadIdx.x;

    __shared__ float hb[NK];
    __shared__ float h[NK];
    __shared__ int   sI[SPAR];
    __shared__ float sL[SPAR][SPAR];
    __shared__ float sC[SPAR];
    __shared__ float g_new[SPAR];
    __shared__ float hst[SPAR];
    __shared__ float rv[8];
    __shared__ int   ri[8];
    __shared__ int   sSel;

    // load h_bar row (each thread owns one float4: columns [4*tid, 4*tid+4))
    {
        const float4 v = reinterpret_cast<const float4*>(hbar + (size_t)b * NK)[tid];
        float4 vn; vn.x = n2n(v.x); vn.y = n2n(v.y); vn.z = n2n(v.z); vn.w = n2n(v.w);
        reinterpret_cast<float4*>(h)[tid] = vn;
        reinterpret_cast<float4*>(hb)[tid] = vn;
    }
    __syncthreads();

    for (int step = 0; step < SPAR; step++) {
        // ---- argmax of scores = masked ? -1 : |h|, first-index tiebreak ----
        float best = -1e30f; int bi = 0;
#pragma unroll
        for (int u = 0; u < 4; u++) {
            const int c = tid * 4 + u;
            float v = fabsf(h[c]);
            bool masked = false;
#pragma unroll
            for (int j = 0; j < SPAR; j++)
                if (j < step && sI[j] == c) masked = true;
            if (masked) v = -1.0f;
            if (v > best || (v == best && c < bi)) { best = v; bi = c; }
        }
#pragma unroll
        for (int off = 16; off; off >>= 1) {
            const float ov = __shfl_down_sync(0xffffffffu, best, off);
            const int   oi = __shfl_down_sync(0xffffffffu, bi, off);
            if (ov > best || (ov == best && oi < bi)) { best = ov; bi = oi; }
        }
        if ((tid & 31) == 0) { rv[tid >> 5] = best; ri[tid >> 5] = bi; }
        __syncthreads();
        if (tid == 0) {
            float bb = rv[0]; int ii = ri[0];
#pragma unroll
            for (int w = 1; w < 8; w++)
                if (rv[w] > bb || (rv[w] == bb && ri[w] < ii)) { bb = rv[w]; ii = ri[w]; }
            sSel = ii;
            sI[step] = ii;
        }
        __syncthreads();
        const int idx = sSel;

        // ---- gather G[I_j, idx] and h_bar[I_j] in parallel lanes ----
        if (tid < step)  g_new[tid] = G[(size_t)sI[tid] * NK + idx];
        if (tid <= step) hst[tid]   = hb[sI[tid]];
        __syncthreads();

        // ---- Cholesky update + cho_solve (serial, tiny) ----
        if (tid == 0) {
            const float dg = G[(size_t)idx * NK + idx];
            if (step == 0) {
                sL[0][0] = sqrtf(fmaxf(dg, CHOL_EPS_F));
            } else {
                float w[SPAR];
                float ss = 0.f;
                for (int j = 0; j < step; j++) {
                    float a = g_new[j];
                    for (int m = 0; m < j; m++) a -= sL[j][m] * w[m];
                    w[j] = a / sL[j][j];
                    sL[step][j] = w[j];
                    ss += w[j] * w[j];
                }
                sL[step][step] = sqrtf(fmaxf(dg - ss, CHOL_EPS_F));
            }
            const int n = step + 1;
            float y[SPAR], x[SPAR];
            for (int j = 0; j < n; j++) {
                float a = hst[j];
                for (int m = 0; m < j; m++) a -= sL[j][m] * y[m];
                y[j] = a / sL[j][j];
            }
            for (int j = n - 1; j >= 0; j--) {
                float a = y[j];
                for (int m = j + 1; m < n; m++) a -= sL[m][j] * x[m];
                x[j] = a / sL[j][j];
            }
            for (int j = 0; j < n; j++) sC[j] = n2n(x[j]);
        }
        __syncthreads();

        // ---- h = n2n(h_bar - coeffs · G[I]) (skip after final step) ----
        if (step < SPAR - 1) {
            float4 a = make_float4(0.f, 0.f, 0.f, 0.f);
#pragma unroll
            for (int j = 0; j < SPAR; j++) {
                if (j > step) break;
                const float c = sC[j];
                const float4 g = reinterpret_cast<const float4*>(
                    G + (size_t)sI[j] * NK)[tid];
                a.x = fmaf(c, g.x, a.x);
                a.y = fmaf(c, g.y, a.y);
                a.z = fmaf(c, g.z, a.z);
                a.w = fmaf(c, g.w, a.w);
            }
            const float4 hbv = reinterpret_cast<const float4*>(hb)[tid];
            float4 hv;
            hv.x = n2n(hbv.x - a.x);
            hv.y = n2n(hbv.y - a.y);
            hv.z = n2n(hbv.z - a.z);
            hv.w = n2n(hbv.w - a.w);
            reinterpret_cast<float4*>(h)[tid] = hv;
            __syncthreads();
        }
    }

    // ---- output: indices (as float) then coefficients ----
    if (tid < SPAR) {
        const size_t iOff = (size_t)b * SPAR + tid;
        const size_t cOff = (size_t)NB * SPAR + (size_t)b * SPAR + tid;
        if (iOff < (size_t)out_size) out[iOff] = (float)sI[tid];
        if (cOff < (size_t)out_size) out[cOff] = sC[tid];
    }
}

// ---------------------------------------------------------------------------
extern "C" void kernel_launch(void* const* d_in, const int* in_sizes, int n_in,
                              void* d_out, int out_size)
{
    const float* X = (const float*)d_in[0];   // [1024, 8192]
    const float* D = (const float*)d_in[1];   // [1024, 1024]
    float* out = (float*)d_out;

    float* Gp;  cudaGetSymbolAddress((void**)&Gp, g_G);
    float* Hp;  cudaGetSymbolAddress((void**)&Hp, g_hbar);

    // fused: h_bar = X^T D  (512 blocks)  +  G = D^T D + eps I (64 blocks)
    const int nBlocks = (NB / 128) * (NK / 128) + (NK / 128) * (NK / 128);
    gemm_fused<<<nBlocks, 256>>>(X, D, Hp, Gp);

    // per-batch OMP
    omp_kernel<<<NB, 256>>>(Gp, Hp, out, out_size);
}